// round 12
// baseline (speedup 1.0000x reference)
#include <cuda_runtime.h>

#define NMAX 16384
#define KNN  16
#define CDIM 64

#define GRES 32                    // grid cells per axis
#define GC   (GRES * GRES * GRES)  // 32768 cells
#define GB   4.5f                  // grid covers [-GB, GB]^3
#define GINVH (GRES / (2.0f * GB))
#define MARGIN 2.5f
#define RCAP2 2.25f                // r^2 cap (outliers -> flagged -> fallback)
#define SURVCAP 64

#define FULLMASK 0xffffffffu
#define FINF __int_as_float(0x7f800000)

// ---- scratch (no allocation allowed) ----
__device__ float4     g_pos4[NMAX];         // orig order (fallback queries)
__device__ ulonglong2 g_pairA[NMAX / 2];    // packed candidates (fallback)
__device__ ulonglong2 g_pairB[NMAX / 2];
__device__ int    g_knn[NMAX * KNN];
__device__ int    g_flag[NMAX];
__device__ float  g_B[NMAX * CDIM];
__device__ float  g_C[NMAX * CDIM];
__device__ float  g_G[NMAX * KNN * CDIM];   // relu'd edge features (64MB)
__device__ ulonglong2 g_W2P2[16 * 64];      // packed W2: [e4][d]
// grid structures
__device__ int    g_cellCnt[GC];
__device__ int    g_cellStart[GC + 1];
__device__ int    g_cellPtr[GC];
__device__ int    g_pcell[NMAX];
__device__ float4 g_spos4[NMAX];            // cell-sorted points
__device__ int    g_sid[NMAX];              // sorted -> orig index

// ---- packed f32x2 helpers ----
__device__ __forceinline__ unsigned long long pk2(float a, float b) {
    unsigned long long r;
    asm("mov.b64 %0, {%1, %2};" : "=l"(r) : "f"(a), "f"(b));
    return r;
}
__device__ __forceinline__ void upk2(unsigned long long v, float& a, float& b) {
    asm("mov.b64 {%0, %1}, %2;" : "=f"(a), "=f"(b) : "l"(v));
}
__device__ __forceinline__ unsigned long long fma2(unsigned long long a,
                                                   unsigned long long b,
                                                   unsigned long long c) {
    unsigned long long r;
    asm("fma.rn.f32x2 %0, %1, %2, %3;" : "=l"(r) : "l"(a), "l"(b), "l"(c));
    return r;
}
__device__ __forceinline__ unsigned long long mul2(unsigned long long a,
                                                   unsigned long long b) {
    unsigned long long r;
    asm("mul.rn.f32x2 %0, %1, %2;" : "=l"(r) : "l"(a), "l"(b));
    return r;
}
__device__ __forceinline__ unsigned long long add2(unsigned long long a,
                                                   unsigned long long b) {
    unsigned long long r;
    asm("add.rn.f32x2 %0, %1, %2;" : "=l"(r) : "l"(a), "l"(b));
    return r;
}
__device__ __forceinline__ unsigned long long umin64(unsigned long long a,
                                                     unsigned long long b) {
    return a < b ? a : b;
}

// predicated shared store (no BSSY/BSYNC; R7 lesson)
__device__ __forceinline__ void sts_pred(unsigned long long* p,
                                         unsigned long long v, int pred) {
    unsigned addr = (unsigned)__cvta_generic_to_shared(p);
    asm volatile(
        "{ .reg .pred q; setp.ne.s32 q, %2, 0; @q st.shared.u64 [%0], %1; }"
        :: "r"(addr), "l"(v), "r"(pred) : "memory");
}

// analytic radius^2: expected #points within r = KNN*MARGIN for pos~N(0,I3)
__device__ __forceinline__ float knn_thr(float qw, int n) {
    const float c0 = (KNN * MARGIN * 3.0f) /
                     (4.0f * 3.14159265f * 0.06349364f * (float)n);
    float r3 = c0 * __expf(0.5f * qw);
    return __powf(r3, 0.6666667f);
}

__device__ __forceinline__ int cell1d(float v) {
    int c = (int)floorf((v + GB) * GINVH);
    return min(GRES - 1, max(0, c));
}

// ============================================================
// Kernel A: zero cell counters
// ============================================================
__global__ void zero_cells_kernel() {
    int i = blockIdx.x * blockDim.x + threadIdx.x;
    if (i < GC) g_cellCnt[i] = 0;
}

// ============================================================
// Kernel 0: pack pos (orig order + fallback pair layout) + bin count
// ============================================================
__global__ void pack_pos_kernel(const float* __restrict__ pos, int n) {
    int i = blockIdx.x * blockDim.x + threadIdx.x;
    if (i < n / 2) {
        int a = 2 * i, b = 2 * i + 1;
        float xa = pos[a * 3 + 0], ya = pos[a * 3 + 1], za = pos[a * 3 + 2];
        float xb = pos[b * 3 + 0], yb = pos[b * 3 + 1], zb = pos[b * 3 + 2];
        float wa = fmaf(xa, xa, fmaf(ya, ya, za * za));
        float wb = fmaf(xb, xb, fmaf(yb, yb, zb * zb));
        g_pos4[a] = make_float4(xa, ya, za, wa);
        g_pos4[b] = make_float4(xb, yb, zb, wb);
        g_pairA[i] = make_ulonglong2(pk2(xa, xb), pk2(ya, yb));
        g_pairB[i] = make_ulonglong2(pk2(za, zb), pk2(wa, wb));
        int ca = (cell1d(za) * GRES + cell1d(ya)) * GRES + cell1d(xa);
        int cb = (cell1d(zb) * GRES + cell1d(yb)) * GRES + cell1d(xb);
        g_pcell[a] = ca;
        g_pcell[b] = cb;
        atomicAdd(&g_cellCnt[ca], 1);
        atomicAdd(&g_cellCnt[cb], 1);
    }
}

// ============================================================
// Kernel B: exclusive prefix sum over GC cells (single block, 1024 thr)
// ============================================================
__global__ __launch_bounds__(1024)
void scan_cells_kernel() {
    __shared__ int sh[1024];
    const int t = threadIdx.x;
    const int base = t * (GC / 1024);          // 32 cells per thread
    int loc[GC / 1024];
    int s = 0;
#pragma unroll
    for (int i = 0; i < GC / 1024; i++) { loc[i] = s; s += g_cellCnt[base + i]; }
    sh[t] = s;
    __syncthreads();
    for (int d = 1; d < 1024; d <<= 1) {       // Hillis-Steele inclusive scan
        int v = (t >= d) ? sh[t - d] : 0;
        __syncthreads();
        sh[t] += v;
        __syncthreads();
    }
    int off = sh[t] - s;                       // exclusive prefix of totals
#pragma unroll
    for (int i = 0; i < GC / 1024; i++) {
        int v = off + loc[i];
        g_cellStart[base + i] = v;
        g_cellPtr[base + i]   = v;
    }
    if (t == 1023) g_cellStart[GC] = off + s;
}

// ============================================================
// Kernel C: scatter points into cell-sorted order
// ============================================================
__global__ void scatter_kernel(int n) {
    int i = blockIdx.x * blockDim.x + threadIdx.x;
    if (i < n) {
        int dst = atomicAdd(&g_cellPtr[g_pcell[i]], 1);
        g_spos4[dst] = g_pos4[i];
        g_sid[dst]   = i;
    }
}

// ============================================================
// Kernel 1a: grid KNN — WARP per sorted query, APPEND-THEN-SELECT.
// Scan is a pure predicated pipeline: per 32-candidate batch one
// ballot + popc-prefix + predicated STS append to a per-warp smem
// survivor list (in-ball set, ~40 entries). NO per-event insert loop
// (the serial shfl-chain inflation seen R8-R11). Selection runs once:
// 16 rounds of warp-wide u64 min-reduce. Keys = (dist_bits<<32 |
// orig_idx) so ties resolve to lowest original index (R9 lesson).
// Certificate: ball fully scanned; cnt<16 or cnt>64 -> exact fallback.
// ============================================================
__global__ __launch_bounds__(256)
void knn_grid_kernel(int n) {
    __shared__ unsigned long long surv[8][SURVCAP];

    const int w    = threadIdx.x >> 5;
    const int lane = threadIdx.x & 31;
    const int s    = blockIdx.x * 8 + w;       // sorted query index

    const float4 qp = g_spos4[s];
    const float thr = fminf(knn_thr(qp.w, n), RCAP2);
    const float r   = sqrtf(thr);

    const int lx = cell1d(qp.x - r), hx = cell1d(qp.x + r);
    const int ly = cell1d(qp.y - r), hy = cell1d(qp.y + r);
    const int lz = cell1d(qp.z - r), hz = cell1d(qp.z + r);

    surv[w][lane]      = ~0ULL;
    surv[w][lane + 32] = ~0ULL;

    int cnt = 0;
    const unsigned below = (1u << lane) - 1u;

    for (int cz = lz; cz <= hz; cz++) {
        for (int cy = ly; cy <= hy; cy++) {
            const int rowb = (cz * GRES + cy) * GRES;
            const int t0 = g_cellStart[rowb + lx];     // warp-uniform
            const int t1 = g_cellStart[rowb + hx + 1];
            for (int tb = t0; tb < t1; tb += 32) {
                const int t  = tb + lane;
                const int tc = min(t, n - 1);
                float4 p = g_spos4[tc];
                int   oj = g_sid[tc];
                float dot = fmaf(qp.x, p.x, fmaf(qp.y, p.y, qp.z * p.z));
                float d = fmaf(-2.0f, dot, qp.w + p.w);   // ref formula
                int valid = (t < t1) & (t != s) & (d < thr);
                unsigned long long key =
                    (((unsigned long long)__float_as_uint(fmaxf(d, 0.0f))) << 32)
                    | (unsigned)oj;
                unsigned m = __ballot_sync(FULLMASK, valid != 0);
                int idx = cnt + __popc(m & below);
                sts_pred(&surv[w][min(idx, SURVCAP - 1)], key,
                         valid & (idx < SURVCAP));
                cnt += __popc(m);
            }
        }
    }
    __syncwarp();

    const int orig = g_sid[s];
    const int bad = (cnt < KNN) | (cnt > SURVCAP);
    if (lane == 0) g_flag[orig] = bad;
    if (!bad) {                                // warp-uniform
        unsigned long long a = surv[w][lane];
        unsigned long long b = surv[w][lane + 32];
        unsigned long long keep = ~0ULL;
#pragma unroll
        for (int rr = 0; rr < KNN; rr++) {
            unsigned long long mn = umin64(a, b);
#pragma unroll
            for (int off = 16; off; off >>= 1)
                mn = umin64(mn, __shfl_xor_sync(FULLMASK, mn, off));
            if (lane == rr) keep = mn;         // SEL, no branch
            if (a == mn) a = ~0ULL;            // keys unique (idx unique)
            if (b == mn) b = ~0ULL;
        }
        if (lane < KNN)
            g_knn[orig * KNN + lane] = (int)(keep & 0xffffffffu);
    }
}

// ============================================================
// Kernel 1b: exact fallback for flagged queries — warp per query,
// warp-distributed sorted top-16 over ALL candidates (key-based).
// ============================================================
__device__ __forceinline__ void warp_insert64(unsigned long long kn,
                                              unsigned long long& bk,
                                              unsigned long long& worst,
                                              int lane) {
    unsigned long long bp = __shfl_up_sync(FULLMASK, bk, 1);
    unsigned gm = __ballot_sync(FULLMASK, (lane < KNN) && (bk > kn));
    int pos = __ffs(gm) - 1;            // gm != 0 since bk[15] > kn
    if (lane < KNN) {
        if (lane > pos)       bk = bp;
        else if (lane == pos) bk = kn;
    }
    worst = __shfl_sync(FULLMASK, bk, KNN - 1);
}

__global__ __launch_bounds__(256)
void knn_fallback_kernel(int n) {
    const int lane = threadIdx.x & 31;
    const int q    = blockIdx.x * 8 + (threadIdx.x >> 5);
    if (g_flag[q] == 0) return;       // warp-uniform

    const float4 qp = g_pos4[q];
    const unsigned long long qx2 = pk2(qp.x, qp.x);
    const unsigned long long qy2 = pk2(qp.y, qp.y);
    const unsigned long long qz2 = pk2(qp.z, qp.z);
    const unsigned long long qw2 = pk2(qp.w, qp.w);
    const unsigned long long M2  = pk2(-2.0f, -2.0f);

    unsigned long long bk = ~0ULL;
    unsigned long long worst = ~0ULL;

    for (int base = 0; base < n / 2; base += 32) {
        ulonglong2 A = g_pairA[base + lane];
        ulonglong2 B = g_pairB[base + lane];
        unsigned long long acc = mul2(qz2, B.x);
        acc = fma2(qy2, A.y, acc);
        acc = fma2(qx2, A.x, acc);
        unsigned long long dd = fma2(M2, acc, add2(qw2, B.y));
        float d0, d1;
        upk2(dd, d0, d1);
        int j0 = 2 * (base + lane);
        unsigned long long k0 =
            (((unsigned long long)__float_as_uint(fmaxf(d0, 0.0f))) << 32)
            | (unsigned)j0;
        unsigned long long k1 =
            (((unsigned long long)__float_as_uint(fmaxf(d1, 0.0f))) << 32)
            | (unsigned)(j0 + 1);
        bool v0 = (k0 < worst) && (j0 != q);
        bool v1 = (k1 < worst) && (j0 + 1 != q);

        unsigned m = __ballot_sync(FULLMASK, v0 | v1);
        while (m) {
            int src = __ffs(m) - 1;
            m &= m - 1;
            unsigned long long e0 = __shfl_sync(FULLMASK, k0, src);
            unsigned long long e1 = __shfl_sync(FULLMASK, k1, src);
            int jj = __shfl_sync(FULLMASK, j0, src);
            if (e0 < worst && jj != q)
                warp_insert64(e0, bk, worst, lane);
            if (e1 < worst && jj + 1 != q)
                warp_insert64(e1, bk, worst, lane);
        }
    }

    if (lane < KNN)
        g_knn[q * KNN + lane] = (int)(bk & 0xffffffffu);
}

// ============================================================
// Kernel 2: B = x @ W1b ; C = x @ (W1a - W1b) + b1  (4-node blocked)
// ============================================================
__global__ __launch_bounds__(256)
void feat_kernel(const float* __restrict__ x,
                 const float* __restrict__ W1,
                 const float* __restrict__ b1, int n) {
    int t   = blockIdx.x * blockDim.x + threadIdx.x;
    int grp = t >> 6;
    int d   = t & 63;
    int n0  = grp * 4;
    if (n0 >= n) return;

    const float* x0 = x + n0 * CDIM;
    float a0 = 0, a1 = 0, a2 = 0, a3 = 0;
    float b0 = 0, b1v = 0, b2v = 0, b3 = 0;
#pragma unroll 8
    for (int c = 0; c < CDIM; c++) {
        float wa = W1[c * CDIM + d];
        float wb = W1[(CDIM + c) * CDIM + d];
        float x0v = x0[c];
        float x1v = x0[CDIM + c];
        float x2v = x0[2 * CDIM + c];
        float x3v = x0[3 * CDIM + c];
        a0 = fmaf(x0v, wa, a0);  b0  = fmaf(x0v, wb, b0);
        a1 = fmaf(x1v, wa, a1);  b1v = fmaf(x1v, wb, b1v);
        a2 = fmaf(x2v, wa, a2);  b2v = fmaf(x2v, wb, b2v);
        a3 = fmaf(x3v, wa, a3);  b3  = fmaf(x3v, wb, b3);
    }
    float bias = b1[d];
    g_B[(n0 + 0) * CDIM + d] = b0;   g_C[(n0 + 0) * CDIM + d] = a0 - b0  + bias;
    g_B[(n0 + 1) * CDIM + d] = b1v;  g_C[(n0 + 1) * CDIM + d] = a1 - b1v + bias;
    g_B[(n0 + 2) * CDIM + d] = b2v;  g_C[(n0 + 2) * CDIM + d] = a2 - b2v + bias;
    g_B[(n0 + 3) * CDIM + d] = b3;   g_C[(n0 + 3) * CDIM + d] = a3 - b3  + bias;
}

// ============================================================
// Kernel D: pack W2 as ulonglong2 [e4][d]  (16KB -> 32KB, L1-resident)
// ============================================================
__global__ void packW2_kernel(const float* __restrict__ W2) {
    int t = blockIdx.x * blockDim.x + threadIdx.x;
    if (t < 16 * 64) {
        int e4 = t >> 6, d = t & 63;
        g_W2P2[t] = make_ulonglong2(
            pk2(W2[(4 * e4 + 0) * CDIM + d], W2[(4 * e4 + 1) * CDIM + d]),
            pk2(W2[(4 * e4 + 2) * CDIM + d], W2[(4 * e4 + 3) * CDIM + d]));
    }
}

// ============================================================
// Kernel 3a: edge gather — materialize G[n][k][d] = relu(C+B) (67MB).
// Pure coalesced streaming: ~20 regs, max occupancy, BW-bound.
// thread -> (n, k, d4): B row coalesced, C L1-hot, G write coalesced.
// ============================================================
__global__ __launch_bounds__(256)
void edge_gather_kernel(int n) {
    int t  = blockIdx.x * 256 + threadIdx.x;   // n*256 threads
    int nn = t >> 8;
    int k  = (t >> 4) & 15;
    int d4 = (t & 15) * 4;
    int j = g_knn[nn * KNN + k];               // uniform per 16 threads
    float4 b = *(const float4*)&g_B[j * CDIM + d4];
    float4 c = *(const float4*)&g_C[nn * CDIM + d4];
    float4 g;
    g.x = fmaxf(c.x + b.x, 0.0f);
    g.y = fmaxf(c.y + b.y, 0.0f);
    g.z = fmaxf(c.z + b.z, 0.0f);
    g.w = fmaxf(c.w + b.w, 0.0f);
    ((float4*)g_G)[t] = g;
}

// ============================================================
// Kernel 3b: edge gemm+max — block 256 thr, 16 nodes/block.
// G tile (4KB contiguous) staged to smem (1 float4/thread, double
// buffered). Thread = (k-group kg, channel d): 4 k-accumulator pairs,
// e4-outer loop: 1 LDG.128 (packed W2, L1) + 4 LDS.128 + 8 FMA2.
// k-max via smem reduce. ~45 regs -> 40+ warps/SM.
// ============================================================
#define NODES2 16
__global__ __launch_bounds__(256)
void edge_gemm_kernel(const float* __restrict__ b2,
                      float* __restrict__ out, int n) {
    __shared__ __align__(16) float Gt[2][KNN][CDIM];   // 8KB
    __shared__ float red[4][CDIM];                     // 1KB

    const int t  = threadIdx.x;
    const int d  = t & 63;
    const int kg = t >> 6;                             // 0..3
    const float b2d = b2[d];
    const int n0 = blockIdx.x * NODES2;

    float4 f4 = ((const float4*)(g_G + (size_t)n0 * (KNN * CDIM)))[t];

    for (int i = 0; i < NODES2; i++) {
        const int buf = i & 1;
        // stage: float idx 4t -> k = t>>4, e = (t&15)*4
        *(float4*)&Gt[buf][t >> 4][(t & 15) * 4] = f4;
        if (i + 1 < NODES2)
            f4 = ((const float4*)(g_G +
                    (size_t)(n0 + i + 1) * (KNN * CDIM)))[t];
        __syncthreads();

        unsigned long long a0[4], a1[4];
#pragma unroll
        for (int kk = 0; kk < 4; kk++) { a0[kk] = 0ULL; a1[kk] = 0ULL; }
#pragma unroll
        for (int e4 = 0; e4 < 16; e4++) {
            ulonglong2 wv = g_W2P2[e4 * 64 + d];       // LDG.128, L1-hot
#pragma unroll
            for (int kk = 0; kk < 4; kk++) {
                ulonglong2 g = *(const ulonglong2*)
                    &Gt[buf][kg * 4 + kk][e4 * 4];     // LDS.128 broadcast
                a0[kk] = fma2(g.x, wv.x, a0[kk]);
                a1[kk] = fma2(g.y, wv.y, a1[kk]);
            }
        }
        float m = -3.4e38f;
#pragma unroll
        for (int kk = 0; kk < 4; kk++) {
            unsigned long long sum = add2(a0[kk], a1[kk]);
            float lo, hi;
            upk2(sum, lo, hi);
            m = fmaxf(m, lo + hi);
        }
        red[kg][d] = m;
        __syncthreads();
        if (t < 64) {
            float mm = fmaxf(fmaxf(red[0][d], red[1][d]),
                             fmaxf(red[2][d], red[3][d]));
            out[(n0 + i) * CDIM + d] = mm + b2d;
        }
        // next iteration's first __syncthreads orders red reuse
    }
}

// ============================================================
extern "C" void kernel_launch(void* const* d_in, const int* in_sizes, int n_in,
                              void* d_out, int out_size) {
    const float* x   = (const float*)d_in[0];
    const float* pos = (const float*)d_in[1];
    const float* W1  = (const float*)d_in[2];
    const float* b1  = (const float*)d_in[3];
    const float* W2  = (const float*)d_in[4];
    const float* b2  = (const float*)d_in[5];
    float* out = (float*)d_out;

    int n = in_sizes[1] / 3;
    if (n > NMAX) n = NMAX;

    zero_cells_kernel<<<GC / 256, 256>>>();
    pack_pos_kernel<<<(n / 2 + 255) / 256, 256>>>(pos, n);
    scan_cells_kernel<<<1, 1024>>>();
    scatter_kernel<<<(n + 255) / 256, 256>>>(n);
    knn_grid_kernel<<<(n + 7) / 8, 256>>>(n);
    knn_fallback_kernel<<<n / 8, 256>>>(n);
    feat_kernel<<<(n * CDIM / 4 + 255) / 256, 256>>>(x, W1, b1, n);
    packW2_kernel<<<4, 256>>>(W2);
    edge_gather_kernel<<<n, 256>>>(n);
    edge_gemm_kernel<<<n / NODES2, 256>>>(b2, out, n);
}

// round 13
// speedup vs baseline: 1.4892x; 1.4892x over previous
#include <cuda_runtime.h>

#define NMAX 16384
#define KNN  16
#define CDIM 64
#define NODES_PER_BLOCK 4

#define GRES 16                    // grid cells per axis (COARSE: row-setup latency was the R11/R12 killer)
#define GC   (GRES * GRES * GRES)  // 4096 cells -> 16KB cellStart, L1-resident
#define GB   4.5f                  // grid covers [-GB, GB]^3
#define GINVH (GRES / (2.0f * GB))
#define MARGIN 2.0f
#define RCAP2 2.25f                // r^2 cap (outliers -> flagged -> fallback)
#define SURVCAP 64

#define FULLMASK 0xffffffffu
#define FINF __int_as_float(0x7f800000)

// ---- scratch (no allocation allowed) ----
__device__ float4     g_pos4[NMAX];         // orig order (fallback queries)
__device__ ulonglong2 g_pairA[NMAX / 2];    // packed candidates (fallback)
__device__ ulonglong2 g_pairB[NMAX / 2];
__device__ int    g_knn[NMAX * KNN];
__device__ int    g_flag[NMAX];
__device__ float  g_B[NMAX * CDIM];
__device__ float  g_C[NMAX * CDIM];
// grid structures
__device__ int    g_cellCnt[GC];
__device__ int    g_cellStart[GC + 1];
__device__ int    g_cellPtr[GC];
__device__ int    g_pcell[NMAX];
__device__ float4 g_spos4[NMAX];            // cell-sorted points
__device__ int    g_sid[NMAX];              // sorted -> orig index

// ---- packed f32x2 helpers ----
__device__ __forceinline__ unsigned long long pk2(float a, float b) {
    unsigned long long r;
    asm("mov.b64 %0, {%1, %2};" : "=l"(r) : "f"(a), "f"(b));
    return r;
}
__device__ __forceinline__ void upk2(unsigned long long v, float& a, float& b) {
    asm("mov.b64 {%0, %1}, %2;" : "=f"(a), "=f"(b) : "l"(v));
}
__device__ __forceinline__ unsigned long long fma2(unsigned long long a,
                                                   unsigned long long b,
                                                   unsigned long long c) {
    unsigned long long r;
    asm("fma.rn.f32x2 %0, %1, %2, %3;" : "=l"(r) : "l"(a), "l"(b), "l"(c));
    return r;
}
__device__ __forceinline__ unsigned long long mul2(unsigned long long a,
                                                   unsigned long long b) {
    unsigned long long r;
    asm("mul.rn.f32x2 %0, %1, %2;" : "=l"(r) : "l"(a), "l"(b));
    return r;
}
__device__ __forceinline__ unsigned long long add2(unsigned long long a,
                                                   unsigned long long b) {
    unsigned long long r;
    asm("add.rn.f32x2 %0, %1, %2;" : "=l"(r) : "l"(a), "l"(b));
    return r;
}
__device__ __forceinline__ unsigned long long umin64(unsigned long long a,
                                                     unsigned long long b) {
    return a < b ? a : b;
}

// predicated shared store (no BSSY/BSYNC; R7 lesson)
__device__ __forceinline__ void sts_pred(unsigned long long* p,
                                         unsigned long long v, int pred) {
    unsigned addr = (unsigned)__cvta_generic_to_shared(p);
    asm volatile(
        "{ .reg .pred q; setp.ne.s32 q, %2, 0; @q st.shared.u64 [%0], %1; }"
        :: "r"(addr), "l"(v), "r"(pred) : "memory");
}

// analytic radius^2: expected #points within r = KNN*MARGIN for pos~N(0,I3)
__device__ __forceinline__ float knn_thr(float qw, int n) {
    const float c0 = (KNN * MARGIN * 3.0f) /
                     (4.0f * 3.14159265f * 0.06349364f * (float)n);
    float r3 = c0 * __expf(0.5f * qw);
    return __powf(r3, 0.6666667f);
}

__device__ __forceinline__ int cell1d(float v) {
    int c = (int)floorf((v + GB) * GINVH);
    return min(GRES - 1, max(0, c));
}

// ============================================================
// Kernel A: zero cell counters
// ============================================================
__global__ void zero_cells_kernel() {
    int i = blockIdx.x * blockDim.x + threadIdx.x;
    if (i < GC) g_cellCnt[i] = 0;
}

// ============================================================
// Kernel 0: pack pos (orig order + fallback pair layout) + bin count
// ============================================================
__global__ void pack_pos_kernel(const float* __restrict__ pos, int n) {
    int i = blockIdx.x * blockDim.x + threadIdx.x;
    if (i < n / 2) {
        int a = 2 * i, b = 2 * i + 1;
        float xa = pos[a * 3 + 0], ya = pos[a * 3 + 1], za = pos[a * 3 + 2];
        float xb = pos[b * 3 + 0], yb = pos[b * 3 + 1], zb = pos[b * 3 + 2];
        float wa = fmaf(xa, xa, fmaf(ya, ya, za * za));
        float wb = fmaf(xb, xb, fmaf(yb, yb, zb * zb));
        g_pos4[a] = make_float4(xa, ya, za, wa);
        g_pos4[b] = make_float4(xb, yb, zb, wb);
        g_pairA[i] = make_ulonglong2(pk2(xa, xb), pk2(ya, yb));
        g_pairB[i] = make_ulonglong2(pk2(za, zb), pk2(wa, wb));
        int ca = (cell1d(za) * GRES + cell1d(ya)) * GRES + cell1d(xa);
        int cb = (cell1d(zb) * GRES + cell1d(yb)) * GRES + cell1d(xb);
        g_pcell[a] = ca;
        g_pcell[b] = cb;
        atomicAdd(&g_cellCnt[ca], 1);
        atomicAdd(&g_cellCnt[cb], 1);
    }
}

// ============================================================
// Kernel B: exclusive prefix sum over GC cells (single block, 1024 thr)
// ============================================================
__global__ __launch_bounds__(1024)
void scan_cells_kernel() {
    __shared__ int sh[1024];
    const int t = threadIdx.x;
    const int base = t * (GC / 1024);          // 4 cells per thread
    int loc[GC / 1024];
    int s = 0;
#pragma unroll
    for (int i = 0; i < GC / 1024; i++) { loc[i] = s; s += g_cellCnt[base + i]; }
    sh[t] = s;
    __syncthreads();
    for (int d = 1; d < 1024; d <<= 1) {       // Hillis-Steele inclusive scan
        int v = (t >= d) ? sh[t - d] : 0;
        __syncthreads();
        sh[t] += v;
        __syncthreads();
    }
    int off = sh[t] - s;                       // exclusive prefix of totals
#pragma unroll
    for (int i = 0; i < GC / 1024; i++) {
        int v = off + loc[i];
        g_cellStart[base + i] = v;
        g_cellPtr[base + i]   = v;
    }
    if (t == 1023) g_cellStart[GC] = off + s;
}

// ============================================================
// Kernel C: scatter points into cell-sorted order
// ============================================================
__global__ void scatter_kernel(int n) {
    int i = blockIdx.x * blockDim.x + threadIdx.x;
    if (i < n) {
        int dst = atomicAdd(&g_cellPtr[g_pcell[i]], 1);
        g_spos4[dst] = g_pos4[i];
        g_sid[dst]   = i;
    }
}

// ============================================================
// Kernel 1a: grid KNN — WARP per sorted query, APPEND-THEN-SELECT.
// COARSE grid (GRES=16): typical box = 2x2x2 cells -> only ~4 (z,y)
// rows of uniform cellStart loads (16KB table, L1-resident); the
// candidate stream per row is long & dense, scanned 32-wide with
// fully-coalesced gathers. Scan = ballot + popc-prefix + predicated
// STS append (no event loop, no divergence). One final selection:
// 16 rounds of warp-wide u64 min-reduce. Keys = (dist_bits<<32 |
// orig_idx): ties resolve to lowest original index (R9 lesson).
// Certificate: ball fully scanned; cnt<16 or cnt>SURVCAP -> fallback.
// ============================================================
__global__ __launch_bounds__(256)
void knn_grid_kernel(int n) {
    __shared__ unsigned long long surv[8][SURVCAP];

    const int w    = threadIdx.x >> 5;
    const int lane = threadIdx.x & 31;
    const int s    = blockIdx.x * 8 + w;       // sorted query index

    const float4 qp = g_spos4[s];
    const float thr = fminf(knn_thr(qp.w, n), RCAP2);
    const float r   = sqrtf(thr);

    const int lx = cell1d(qp.x - r), hx = cell1d(qp.x + r);
    const int ly = cell1d(qp.y - r), hy = cell1d(qp.y + r);
    const int lz = cell1d(qp.z - r), hz = cell1d(qp.z + r);

    surv[w][lane]      = ~0ULL;
    surv[w][lane + 32] = ~0ULL;

    int cnt = 0;
    const unsigned below = (1u << lane) - 1u;

    for (int cz = lz; cz <= hz; cz++) {
        for (int cy = ly; cy <= hy; cy++) {
            const int rowb = (cz * GRES + cy) * GRES;
            const int t0 = g_cellStart[rowb + lx];     // warp-uniform, L1
            const int t1 = g_cellStart[rowb + hx + 1];
            for (int tb = t0; tb < t1; tb += 32) {
                const int t  = tb + lane;
                const int tc = min(t, n - 1);
                float4 p = g_spos4[tc];                // coalesced LDG.128
                int   oj = g_sid[tc];
                float dot = fmaf(qp.x, p.x, fmaf(qp.y, p.y, qp.z * p.z));
                float d = fmaf(-2.0f, dot, qp.w + p.w);   // ref formula
                int valid = (t < t1) & (t != s) & (d < thr);
                unsigned long long key =
                    (((unsigned long long)__float_as_uint(fmaxf(d, 0.0f))) << 32)
                    | (unsigned)oj;
                unsigned m = __ballot_sync(FULLMASK, valid != 0);
                int idx = cnt + __popc(m & below);
                sts_pred(&surv[w][min(idx, SURVCAP - 1)], key,
                         valid & (idx < SURVCAP));
                cnt += __popc(m);
            }
        }
    }
    __syncwarp();

    const int orig = g_sid[s];
    const int bad = (cnt < KNN) | (cnt > SURVCAP);
    if (lane == 0) g_flag[orig] = bad;
    if (!bad) {                                // warp-uniform
        unsigned long long a = surv[w][lane];
        unsigned long long b = surv[w][lane + 32];
        unsigned long long keep = ~0ULL;
#pragma unroll
        for (int rr = 0; rr < KNN; rr++) {
            unsigned long long mn = umin64(a, b);
#pragma unroll
            for (int off = 16; off; off >>= 1)
                mn = umin64(mn, __shfl_xor_sync(FULLMASK, mn, off));
            if (lane == rr) keep = mn;         // SEL, no branch
            if (a == mn) a = ~0ULL;            // keys unique (idx unique)
            if (b == mn) b = ~0ULL;
        }
        if (lane < KNN)
            g_knn[orig * KNN + lane] = (int)(keep & 0xffffffffu);
    }
}

// ============================================================
// Kernel 1b: exact fallback for flagged queries — warp per query,
// warp-distributed sorted top-16 over ALL candidates (key-based).
// ============================================================
__device__ __forceinline__ void warp_insert64(unsigned long long kn,
                                              unsigned long long& bk,
                                              unsigned long long& worst,
                                              int lane) {
    unsigned long long bp = __shfl_up_sync(FULLMASK, bk, 1);
    unsigned gm = __ballot_sync(FULLMASK, (lane < KNN) && (bk > kn));
    int pos = __ffs(gm) - 1;            // gm != 0 since bk[15] > kn
    if (lane < KNN) {
        if (lane > pos)       bk = bp;
        else if (lane == pos) bk = kn;
    }
    worst = __shfl_sync(FULLMASK, bk, KNN - 1);
}

__global__ __launch_bounds__(256)
void knn_fallback_kernel(int n) {
    const int lane = threadIdx.x & 31;
    const int q    = blockIdx.x * 8 + (threadIdx.x >> 5);
    if (g_flag[q] == 0) return;       // warp-uniform

    const float4 qp = g_pos4[q];
    const unsigned long long qx2 = pk2(qp.x, qp.x);
    const unsigned long long qy2 = pk2(qp.y, qp.y);
    const unsigned long long qz2 = pk2(qp.z, qp.z);
    const unsigned long long qw2 = pk2(qp.w, qp.w);
    const unsigned long long M2  = pk2(-2.0f, -2.0f);

    unsigned long long bk = ~0ULL;
    unsigned long long worst = ~0ULL;

    for (int base = 0; base < n / 2; base += 32) {
        ulonglong2 A = g_pairA[base + lane];
        ulonglong2 B = g_pairB[base + lane];
        unsigned long long acc = mul2(qz2, B.x);
        acc = fma2(qy2, A.y, acc);
        acc = fma2(qx2, A.x, acc);
        unsigned long long dd = fma2(M2, acc, add2(qw2, B.y));
        float d0, d1;
        upk2(dd, d0, d1);
        int j0 = 2 * (base + lane);
        unsigned long long k0 =
            (((unsigned long long)__float_as_uint(fmaxf(d0, 0.0f))) << 32)
            | (unsigned)j0;
        unsigned long long k1 =
            (((unsigned long long)__float_as_uint(fmaxf(d1, 0.0f))) << 32)
            | (unsigned)(j0 + 1);
        bool v0 = (k0 < worst) && (j0 != q);
        bool v1 = (k1 < worst) && (j0 + 1 != q);

        unsigned m = __ballot_sync(FULLMASK, v0 | v1);
        while (m) {
            int src = __ffs(m) - 1;
            m &= m - 1;
            unsigned long long e0 = __shfl_sync(FULLMASK, k0, src);
            unsigned long long e1 = __shfl_sync(FULLMASK, k1, src);
            int jj = __shfl_sync(FULLMASK, j0, src);
            if (e0 < worst && jj != q)
                warp_insert64(e0, bk, worst, lane);
            if (e1 < worst && jj + 1 != q)
                warp_insert64(e1, bk, worst, lane);
        }
    }

    if (lane < KNN)
        g_knn[q * KNN + lane] = (int)(bk & 0xffffffffu);
}

// ============================================================
// Kernel 2: B = x @ W1b ; C = x @ (W1a - W1b) + b1  (4-node blocked)
// ============================================================
__global__ __launch_bounds__(256)
void feat_kernel(const float* __restrict__ x,
                 const float* __restrict__ W1,
                 const float* __restrict__ b1, int n) {
    int t   = blockIdx.x * blockDim.x + threadIdx.x;
    int grp = t >> 6;
    int d   = t & 63;
    int n0  = grp * 4;
    if (n0 >= n) return;

    const float* x0 = x + n0 * CDIM;
    float a0 = 0, a1 = 0, a2 = 0, a3 = 0;
    float b0 = 0, b1v = 0, b2v = 0, b3 = 0;
#pragma unroll 8
    for (int c = 0; c < CDIM; c++) {
        float wa = W1[c * CDIM + d];
        float wb = W1[(CDIM + c) * CDIM + d];
        float x0v = x0[c];
        float x1v = x0[CDIM + c];
        float x2v = x0[2 * CDIM + c];
        float x3v = x0[3 * CDIM + c];
        a0 = fmaf(x0v, wa, a0);  b0  = fmaf(x0v, wb, b0);
        a1 = fmaf(x1v, wa, a1);  b1v = fmaf(x1v, wb, b1v);
        a2 = fmaf(x2v, wa, a2);  b2v = fmaf(x2v, wb, b2v);
        a3 = fmaf(x3v, wa, a3);  b3  = fmaf(x3v, wb, b3);
    }
    float bias = b1[d];
    g_B[(n0 + 0) * CDIM + d] = b0;   g_C[(n0 + 0) * CDIM + d] = a0 - b0  + bias;
    g_B[(n0 + 1) * CDIM + d] = b1v;  g_C[(n0 + 1) * CDIM + d] = a1 - b1v + bias;
    g_B[(n0 + 2) * CDIM + d] = b2v;  g_C[(n0 + 2) * CDIM + d] = a2 - b2v + bias;
    g_B[(n0 + 3) * CDIM + d] = b3;   g_C[(n0 + 3) * CDIM + d] = a3 - b3  + bias;
}

// ============================================================
// Kernel 3: edge — PROVEN R8 monolithic e-outer kernel (88us known):
// W2 streams from L1 (coalesced), k-accumulators in 8 packed u64 regs,
// g from transposed smem tile, next node's B-rows prefetched under
// phase 2. (R12's split-edge with the 67MB G round-trip lost; reverted.)
// ============================================================
#define GSTRIDE 20
__global__ __launch_bounds__(64)
void edge_kernel(const float* __restrict__ W2,
                 const float* __restrict__ b2,
                 float* __restrict__ out, int n) {
    __shared__ __align__(16) float gsT[2][CDIM][GSTRIDE];
    const int d = threadIdx.x;
    const float b2d = b2[d];
    const int n0 = blockIdx.x * NODES_PER_BLOCK;

    float bv[KNN];
    float cv;
    {
        const int4* jr = (const int4*)&g_knn[n0 * KNN];
        int4 j4[4];
#pragma unroll
        for (int v = 0; v < 4; v++) j4[v] = jr[v];
        const int* jv = (const int*)j4;
        cv = g_C[n0 * CDIM + d];
#pragma unroll
        for (int k = 0; k < KNN; k++)
            bv[k] = g_B[jv[k] * CDIM + d];
    }

    for (int i = 0; i < NODES_PER_BLOCK; i++) {
        const int buf = i & 1;
        const int nn  = n0 + i;

#pragma unroll
        for (int k2 = 0; k2 < KNN / 2; k2++) {
            float2 gg;
            gg.x = fmaxf(cv + bv[2 * k2],     0.0f);
            gg.y = fmaxf(cv + bv[2 * k2 + 1], 0.0f);
            *(float2*)&gsT[buf][d][2 * k2] = gg;
        }

        if (i + 1 < NODES_PER_BLOCK) {
            const int nn1 = nn + 1;
            const int4* jr = (const int4*)&g_knn[nn1 * KNN];
            int4 j4[4];
#pragma unroll
            for (int v = 0; v < 4; v++) j4[v] = jr[v];
            const int* jv = (const int*)j4;
            cv = g_C[nn1 * CDIM + d];
#pragma unroll
            for (int k = 0; k < KNN; k++)
                bv[k] = g_B[jv[k] * CDIM + d];
        }
        __syncthreads();

        unsigned long long acc[8];
#pragma unroll
        for (int j = 0; j < 8; j++) acc[j] = 0ULL;
#pragma unroll 8
        for (int e = 0; e < CDIM; e++) {
            float wv = W2[e * CDIM + d];
            unsigned long long w2 = pk2(wv, wv);
            const ulonglong2* gp = (const ulonglong2*)&gsT[buf][e][0];
            ulonglong2 Ga = gp[0];
            ulonglong2 Gb = gp[1];
            acc[0] = fma2(Ga.x, w2, acc[0]);
            acc[1] = fma2(Ga.y, w2, acc[1]);
            acc[2] = fma2(Gb.x, w2, acc[2]);
            acc[3] = fma2(Gb.y, w2, acc[3]);
            const ulonglong2* gq = (const ulonglong2*)&gsT[buf][e][8];
            ulonglong2 Gc = gq[0];
            ulonglong2 Gd = gq[1];
            acc[4] = fma2(Gc.x, w2, acc[4]);
            acc[5] = fma2(Gd.x, w2, acc[5]);
            acc[6] = fma2(Gc.y, w2, acc[6]);
            acc[7] = fma2(Gd.y, w2, acc[7]);
        }
        float m = -3.4e38f;
#pragma unroll
        for (int j = 0; j < 8; j++) {
            float lo, hi;
            upk2(acc[j], lo, hi);
            m = fmaxf(m, fmaxf(lo, hi));
        }
        out[nn * CDIM + d] = m + b2d;
    }
}

// ============================================================
extern "C" void kernel_launch(void* const* d_in, const int* in_sizes, int n_in,
                              void* d_out, int out_size) {
    const float* x   = (const float*)d_in[0];
    const float* pos = (const float*)d_in[1];
    const float* W1  = (const float*)d_in[2];
    const float* b1  = (const float*)d_in[3];
    const float* W2  = (const float*)d_in[4];
    const float* b2  = (const float*)d_in[5];
    float* out = (float*)d_out;

    int n = in_sizes[1] / 3;
    if (n > NMAX) n = NMAX;

    zero_cells_kernel<<<GC / 256, 256>>>();
    pack_pos_kernel<<<(n / 2 + 255) / 256, 256>>>(pos, n);
    scan_cells_kernel<<<1, 1024>>>();
    scatter_kernel<<<(n + 255) / 256, 256>>>(n);
    knn_grid_kernel<<<(n + 7) / 8, 256>>>(n);
    knn_fallback_kernel<<<n / 8, 256>>>(n);
    feat_kernel<<<(n * CDIM / 4 + 255) / 256, 256>>>(x, W1, b1, n);
    edge_kernel<<<n / NODES_PER_BLOCK, CDIM>>>(W2, b2, out, n);
}